// round 7
// baseline (speedup 1.0000x reference)
#include <cuda_runtime.h>
#include <cuda_bf16.h>
#include <stdint.h>
#include <math.h>

// ---------------- problem constants ----------------
#define BATCH   8
#define SEQ     4096
#define DM      1024
#define NS      256
#define M_ROWS  (BATCH*SEQ)     // 32768
#define CHUNK   128
#define NCHUNK  (SEQ/CHUNK)     // 32

// ---------------- scratch ----------------
__device__ float g_a[M_ROWS * NS];
__device__ float g_b[M_ROWS * NS];
__device__ float g_Aagg[BATCH * NCHUNK * NS];
__device__ float g_Bagg[BATCH * NCHUNK * NS];
__device__ float g_carry[BATCH * NCHUNK * NS];

__device__ __nv_bfloat16 g_xhi[M_ROWS * DM], g_xlo[M_ROWS * DM];
__device__ __nv_bfloat16 g_hhi[M_ROWS * NS], g_hlo[M_ROWS * NS];
__device__ __nv_bfloat16 g_wahi[NS * DM],  g_walo[NS * DM];
__device__ __nv_bfloat16 g_bwhi[NS * DM],  g_bwlo[NS * DM];
__device__ __nv_bfloat16 g_chi[DM * NS],   g_clo[DM * NS];
__device__ __nv_bfloat16 g_dhi[DM * DM],   g_dlo[DM * DM];

// ---------------- GEMM config ----------------
// CTA tile 128x256, BK=32 bf16, 8 warps (2x4) each 64x64.
// smem rows padded to 40 bf16 (80 B) -> 16B-aligned + conflict-free ldmatrix.
// 3-stage cp.async ring, one __syncthreads per slab.
#define LDS_EL  40
#define ROW_B   (LDS_EL*2)          // 80 B
#define A_T     (128 * ROW_B)       // 10240 B per A tile
#define B_T     (256 * ROW_B)       // 20480 B per B tile
#define STAGE   (2*A_T + 2*B_T)     // 61440 B  (Ahi,Alo,Bhi,Blo)
#define NSTAGE  3
#define SMEM_TOTAL (NSTAGE * STAGE) // 184320 B
#define OFF_AHI 0
#define OFF_ALO A_T
#define OFF_BHI (2*A_T)
#define OFF_BLO (2*A_T + B_T)

// ---------------- PTX helpers ----------------
__device__ __forceinline__ uint32_t smem_u32(const void* p) {
    uint32_t a;
    asm("{ .reg .u64 t; cvta.to.shared.u64 t, %1; cvt.u32.u64 %0, t; }" : "=r"(a) : "l"(p));
    return a;
}
__device__ __forceinline__ void cp16(uint32_t d, const void* s) {
    asm volatile("cp.async.cg.shared.global [%0], [%1], 16;" :: "r"(d), "l"(s));
}
#define CP_COMMIT() asm volatile("cp.async.commit_group;" ::: "memory")
#define CP_WAIT(N)  asm volatile("cp.async.wait_group %0;" :: "n"(N) : "memory")

__device__ __forceinline__ void ldm4(uint32_t* r, uint32_t a) {
    asm volatile("ldmatrix.sync.aligned.m8n8.x4.shared.b16 {%0,%1,%2,%3}, [%4];"
        : "=r"(r[0]), "=r"(r[1]), "=r"(r[2]), "=r"(r[3]) : "r"(a));
}
__device__ __forceinline__ void mma16(float* c, const uint32_t* a, const uint32_t* b) {
    asm volatile("mma.sync.aligned.m16n8k16.row.col.f32.bf16.bf16.f32 "
        "{%0,%1,%2,%3}, {%4,%5,%6,%7}, {%8,%9}, {%0,%1,%2,%3};"
        : "+f"(c[0]), "+f"(c[1]), "+f"(c[2]), "+f"(c[3])
        : "r"(a[0]), "r"(a[1]), "r"(a[2]), "r"(a[3]), "r"(b[0]), "r"(b[1]));
}

// ---------------- per-slab compute: warp 64x64, 3-pass bf16 compensation ----------------
__device__ __forceinline__ void compute_slab(uint32_t stg, float acc[4][8][4],
                                             int wr, int wc, int lane)
{
    const uint32_t aoff = ((wr * 64 + (lane & 15)) * LDS_EL + (lane >> 4) * 8) * 2;
    const uint32_t boff = ((wc * 64 + (lane & 15)) * LDS_EL + (lane >> 4) * 8) * 2;
    #pragma unroll
    for (int ks = 0; ks < 2; ks++) {
        const uint32_t kb = ks * 32;   // 16 bf16 = 32 B
        uint32_t ahi[4][4], alo[4][4];
        #pragma unroll
        for (int i = 0; i < 4; i++) ldm4(ahi[i], stg + OFF_AHI + aoff + kb + i * 16 * ROW_B);
        #pragma unroll
        for (int i = 0; i < 4; i++) ldm4(alo[i], stg + OFF_ALO + aoff + kb + i * 16 * ROW_B);

        #pragma unroll
        for (int jb = 0; jb < 2; jb++) {
            const uint32_t jrow = jb * 32 * ROW_B;
            uint32_t bh[4][2], bl[4][2];
            {
                uint32_t t0[4], t1[4];
                ldm4(t0, stg + OFF_BHI + boff + kb + jrow);
                ldm4(t1, stg + OFF_BHI + boff + kb + jrow + 16 * ROW_B);
                bh[0][0] = t0[0]; bh[0][1] = t0[2]; bh[1][0] = t0[1]; bh[1][1] = t0[3];
                bh[2][0] = t1[0]; bh[2][1] = t1[2]; bh[3][0] = t1[1]; bh[3][1] = t1[3];
            }
            #pragma unroll
            for (int j = 0; j < 4; j++)
                #pragma unroll
                for (int i = 0; i < 4; i++) mma16(acc[i][jb*4+j], ahi[i], bh[j]);   // hi*hi
            {
                uint32_t t0[4], t1[4];
                ldm4(t0, stg + OFF_BLO + boff + kb + jrow);
                ldm4(t1, stg + OFF_BLO + boff + kb + jrow + 16 * ROW_B);
                bl[0][0] = t0[0]; bl[0][1] = t0[2]; bl[1][0] = t0[1]; bl[1][1] = t0[3];
                bl[2][0] = t1[0]; bl[2][1] = t1[2]; bl[3][0] = t1[1]; bl[3][1] = t1[3];
            }
            #pragma unroll
            for (int j = 0; j < 4; j++)
                #pragma unroll
                for (int i = 0; i < 4; i++) mma16(acc[i][jb*4+j], ahi[i], bl[j]);   // hi*lo
            #pragma unroll
            for (int j = 0; j < 4; j++)
                #pragma unroll
                for (int i = 0; i < 4; i++) mma16(acc[i][jb*4+j], alo[i], bh[j]);   // lo*hi
        }
    }
}

// ---------------- pipelined GEMM segment (3-stage ring, 1 sync/slab) ----------------
__device__ __forceinline__ void gemm_pipe(
    const __nv_bfloat16* __restrict__ Ah, const __nv_bfloat16* __restrict__ Al, int lda, int m0,
    const __nv_bfloat16* __restrict__ Bh, const __nv_bfloat16* __restrict__ Bl, int ldb, int n0,
    int K, uint32_t sb, float acc[4][8][4])
{
    const int tid = threadIdx.x;
    const int warp = tid >> 5, lane = tid & 31;
    const int wr = warp >> 2, wc = warp & 3;

    const __nv_bfloat16* a0 = Ah + (size_t)m0 * lda;
    const __nv_bfloat16* a1 = Al + (size_t)m0 * lda;
    const __nv_bfloat16* b0 = Bh + (size_t)n0 * ldb;
    const __nv_bfloat16* b1 = Bl + (size_t)n0 * ldb;

    auto issue = [&](int slab, int buf) {
        const int k0 = slab * 32;
        const uint32_t db = sb + buf * STAGE;
        #pragma unroll
        for (int t = 0; t < 12; t++) {
            int id = tid + t * 256;          // 3072 16B-chunks total
            const __nv_bfloat16* s;
            uint32_t d;
            if (id < 1024) {                 // A tiles: 512 chunks each
                int half = id >> 9;
                int c = id & 511;
                int row = c >> 2, seg = c & 3;
                s = (half ? a1 : a0) + (size_t)row * lda + k0 + seg * 8;
                d = db + half * A_T + row * ROW_B + seg * 16;
            } else {                         // B tiles: 1024 chunks each
                int id2 = id - 1024;
                int half = id2 >> 10;
                int c = id2 & 1023;
                int row = c >> 2, seg = c & 3;
                s = (half ? b1 : b0) + (size_t)row * ldb + k0 + seg * 8;
                d = db + OFF_BHI + half * B_T + row * ROW_B + seg * 16;
            }
            cp16(d, s);
        }
        CP_COMMIT();
    };

    const int nslab = K / 32;                // >= 8 always
    issue(0, 0);
    issue(1, 1);
    int buf = 0;
    for (int s = 0; s < nslab; s++) {
        if (s + 1 < nslab) { CP_WAIT(1); } else { CP_WAIT(0); }
        __syncthreads();
        if (s + 2 < nslab) {
            int nb = buf + 2; if (nb >= NSTAGE) nb -= NSTAGE;
            issue(s + 2, nb);
        }
        compute_slab(sb + buf * STAGE, acc, wr, wc, lane);
        if (++buf == NSTAGE) buf = 0;
    }
    __syncthreads();                         // protect last-read buffer before reuse
}

// ---------------- kernels ----------------
__global__ void split_kernel(const float* __restrict__ src,
                             __nv_bfloat16* __restrict__ hi,
                             __nv_bfloat16* __restrict__ lo, int n)
{
    int i = (blockIdx.x * blockDim.x + threadIdx.x) * 4;
    if (i >= n) return;
    float4 v = *(const float4*)(src + i);
    __nv_bfloat16 h[4], l[4];
    h[0] = __float2bfloat16(v.x); l[0] = __float2bfloat16(v.x - __bfloat162float(h[0]));
    h[1] = __float2bfloat16(v.y); l[1] = __float2bfloat16(v.y - __bfloat162float(h[1]));
    h[2] = __float2bfloat16(v.z); l[2] = __float2bfloat16(v.z - __bfloat162float(h[2]));
    h[3] = __float2bfloat16(v.w); l[3] = __float2bfloat16(v.w - __bfloat162float(h[3]));
    *(uint2*)(hi + i) = *(uint2*)h;
    *(uint2*)(lo + i) = *(uint2*)l;
}

__global__ __launch_bounds__(256, 1)
void proj_kernel(const float* __restrict__ bias)
{
    extern __shared__ char smem[];
    uint32_t sb = smem_u32(smem);
    float acc[4][8][4] = {};

    const int m0 = blockIdx.x * 128;
    const bool is_a = (blockIdx.y == 0);
    const __nv_bfloat16* Wh = is_a ? g_wahi : g_bwhi;
    const __nv_bfloat16* Wl = is_a ? g_walo : g_bwlo;

    gemm_pipe(g_xhi, g_xlo, DM, m0, Wh, Wl, DM, 0, DM, sb, acc);

    float* dst = is_a ? g_a : g_b;
    const int warp = threadIdx.x >> 5, lane = threadIdx.x & 31;
    const int wr = warp >> 2, wc = warp & 3;
    const int gq = lane >> 2, tq = lane & 3;

    #pragma unroll
    for (int i = 0; i < 4; i++) {
        #pragma unroll
        for (int j = 0; j < 8; j++) {
            const int row = m0 + wr * 64 + i * 16 + gq;
            const int col = wc * 64 + j * 8 + tq * 2;
            float v0 = acc[i][j][0], v1 = acc[i][j][1];
            float v2 = acc[i][j][2], v3 = acc[i][j][3];
            if (is_a) {
                float b0 = bias[col], b1 = bias[col + 1];
                v0 = 1.0f / (1.0f + __expf(-(v0 + b0)));
                v1 = 1.0f / (1.0f + __expf(-(v1 + b1)));
                v2 = 1.0f / (1.0f + __expf(-(v2 + b0)));
                v3 = 1.0f / (1.0f + __expf(-(v3 + b1)));
            }
            *(float2*)&dst[(size_t)row * NS + col]       = make_float2(v0, v1);
            *(float2*)&dst[(size_t)(row + 8) * NS + col] = make_float2(v2, v3);
        }
    }
}

__global__ __launch_bounds__(256, 1)
void out_kernel(float* __restrict__ Y)
{
    extern __shared__ char smem[];
    uint32_t sb = smem_u32(smem);
    float acc[4][8][4] = {};

    const int m0 = blockIdx.x * 128;
    const int n0 = blockIdx.y * 256;

    gemm_pipe(g_hhi, g_hlo, NS, m0, g_chi, g_clo, NS, n0, NS, sb, acc); // h @ C^T
    gemm_pipe(g_xhi, g_xlo, DM, m0, g_dhi, g_dlo, DM, n0, DM, sb, acc); // x @ D^T

    const int warp = threadIdx.x >> 5, lane = threadIdx.x & 31;
    const int wr = warp >> 2, wc = warp & 3;
    const int gq = lane >> 2, tq = lane & 3;

    #pragma unroll
    for (int i = 0; i < 4; i++) {
        #pragma unroll
        for (int j = 0; j < 8; j++) {
            const int row = m0 + wr * 64 + i * 16 + gq;
            const int col = n0 + wc * 64 + j * 8 + tq * 2;
            *(float2*)&Y[(size_t)row * DM + col]       = make_float2(acc[i][j][0], acc[i][j][1]);
            *(float2*)&Y[(size_t)(row + 8) * DM + col] = make_float2(acc[i][j][2], acc[i][j][3]);
        }
    }
}

// ---------------- scan ----------------
__global__ void scan_agg()
{
    const int bc = blockIdx.x, n = threadIdx.x;
    const int b = bc / NCHUNK, c = bc % NCHUNK;
    size_t base = ((size_t)b * SEQ + (size_t)c * CHUNK) * NS + n;
    float A = 1.0f, Bv = 0.0f;
    for (int s = 0; s < CHUNK; s++) {
        size_t idx = base + (size_t)s * NS;
        float a = g_a[idx], bb = g_b[idx];
        A = a * A; Bv = a * Bv + bb;
    }
    g_Aagg[(size_t)bc * NS + n] = A;
    g_Bagg[(size_t)bc * NS + n] = Bv;
}

__global__ void scan_carry()
{
    const int b = blockIdx.x, n = threadIdx.x;
    float h = 0.0f;
    for (int c = 0; c < NCHUNK; c++) {
        size_t idx = ((size_t)b * NCHUNK + c) * NS + n;
        g_carry[idx] = h;
        h = g_Aagg[idx] * h + g_Bagg[idx];
    }
}

__global__ void scan_apply()
{
    const int bc = blockIdx.x, n = threadIdx.x;
    const int b = bc / NCHUNK, c = bc % NCHUNK;
    float h = g_carry[(size_t)bc * NS + n];
    size_t base = ((size_t)b * SEQ + (size_t)c * CHUNK) * NS + n;
    for (int s = 0; s < CHUNK; s++) {
        size_t idx = base + (size_t)s * NS;
        h = g_a[idx] * h + g_b[idx];
        __nv_bfloat16 hh = __float2bfloat16(h);
        g_hhi[idx] = hh;
        g_hlo[idx] = __float2bfloat16(h - __bfloat162float(hh));
    }
}

// ---------------- launch ----------------
extern "C" void kernel_launch(void* const* d_in, const int* in_sizes, int n_in,
                              void* d_out, int out_size)
{
    const float* x    = (const float*)d_in[0];
    const float* Wa_w = (const float*)d_in[1];
    const float* Wa_b = (const float*)d_in[2];
    const float* B_w  = (const float*)d_in[3];
    const float* C_w  = (const float*)d_in[4];
    const float* D_w  = (const float*)d_in[5];
    float* y = (float*)d_out;

    cudaFuncSetAttribute(proj_kernel, cudaFuncAttributeMaxDynamicSharedMemorySize, SMEM_TOTAL);
    cudaFuncSetAttribute(out_kernel,  cudaFuncAttributeMaxDynamicSharedMemorySize, SMEM_TOTAL);

    __nv_bfloat16 *xhi, *xlo, *wahi, *walo, *bwhi, *bwlo, *chi, *clo, *dhi, *dlo;
    cudaGetSymbolAddress((void**)&xhi,  g_xhi);  cudaGetSymbolAddress((void**)&xlo,  g_xlo);
    cudaGetSymbolAddress((void**)&wahi, g_wahi); cudaGetSymbolAddress((void**)&walo, g_walo);
    cudaGetSymbolAddress((void**)&bwhi, g_bwhi); cudaGetSymbolAddress((void**)&bwlo, g_bwlo);
    cudaGetSymbolAddress((void**)&chi,  g_chi);  cudaGetSymbolAddress((void**)&clo,  g_clo);
    cudaGetSymbolAddress((void**)&dhi,  g_dhi);  cudaGetSymbolAddress((void**)&dlo,  g_dlo);

    split_kernel<<<(M_ROWS*DM/4 + 255)/256, 256>>>(x,    xhi,  xlo,  M_ROWS*DM);
    split_kernel<<<(NS*DM/4     + 255)/256, 256>>>(Wa_w, wahi, walo, NS*DM);
    split_kernel<<<(NS*DM/4     + 255)/256, 256>>>(B_w,  bwhi, bwlo, NS*DM);
    split_kernel<<<(DM*NS/4     + 255)/256, 256>>>(C_w,  chi,  clo,  DM*NS);
    split_kernel<<<(DM*DM/4     + 255)/256, 256>>>(D_w,  dhi,  dlo,  DM*DM);

    dim3 blk(256);
    dim3 gproj(M_ROWS / 128, 2);          // 256 x 2 (a | b), full NS per tile
    proj_kernel<<<gproj, blk, SMEM_TOTAL>>>(Wa_b);

    scan_agg  <<<BATCH * NCHUNK, NS>>>();
    scan_carry<<<BATCH, NS>>>();
    scan_apply<<<BATCH * NCHUNK, NS>>>();

    dim3 gout(M_ROWS / 128, DM / 256);    // 256 x 4
    out_kernel<<<gout, blk, SMEM_TOTAL>>>(y);
}

// round 8
// speedup vs baseline: 1.1016x; 1.1016x over previous
#include <cuda_runtime.h>
#include <cuda_bf16.h>
#include <stdint.h>
#include <math.h>

// ---------------- problem constants ----------------
#define BATCH   8
#define SEQ     4096
#define DM      1024
#define NS      256
#define M_ROWS  (BATCH*SEQ)     // 32768
#define CHUNK   128
#define NCHUNK  (SEQ/CHUNK)     // 32

// ---------------- scratch ----------------
__device__ float g_a[M_ROWS * NS];
__device__ float g_b[M_ROWS * NS];
__device__ float g_Aagg[BATCH * NCHUNK * NS];
__device__ float g_Bagg[BATCH * NCHUNK * NS];
__device__ float g_carry[BATCH * NCHUNK * NS];

__device__ __nv_bfloat16 g_xhi[M_ROWS * DM], g_xlo[M_ROWS * DM];
__device__ __nv_bfloat16 g_hhi[M_ROWS * NS], g_hlo[M_ROWS * NS];
__device__ __nv_bfloat16 g_wahi[NS * DM],  g_walo[NS * DM];
__device__ __nv_bfloat16 g_bwhi[NS * DM],  g_bwlo[NS * DM];
__device__ __nv_bfloat16 g_chi[DM * NS],   g_clo[DM * NS];
__device__ __nv_bfloat16 g_dhi[DM * DM],   g_dlo[DM * DM];

// ---------------- GEMM config (R6 known-good: 128x128, 2 CTA/SM) ----------------
#define LDS_EL  40
#define A_SZ    (128 * LDS_EL * 2)      // 10240 B
#define STAGE   (4 * A_SZ)              // 40960 B
#define SMEM_TOTAL (2 * STAGE)          // 81920 B

// ---------------- PTX helpers ----------------
__device__ __forceinline__ uint32_t smem_u32(const void* p) {
    uint32_t a;
    asm("{ .reg .u64 t; cvta.to.shared.u64 t, %1; cvt.u32.u64 %0, t; }" : "=r"(a) : "l"(p));
    return a;
}
__device__ __forceinline__ void cp16(uint32_t d, const void* s) {
    asm volatile("cp.async.cg.shared.global [%0], [%1], 16;" :: "r"(d), "l"(s));
}
#define CP_COMMIT() asm volatile("cp.async.commit_group;" ::: "memory")
#define CP_WAIT(N)  asm volatile("cp.async.wait_group %0;" :: "n"(N) : "memory")

__device__ __forceinline__ void ldm4(uint32_t* r, uint32_t a) {
    asm volatile("ldmatrix.sync.aligned.m8n8.x4.shared.b16 {%0,%1,%2,%3}, [%4];"
        : "=r"(r[0]), "=r"(r[1]), "=r"(r[2]), "=r"(r[3]) : "r"(a));
}
__device__ __forceinline__ void mma16(float* c, const uint32_t* a, const uint32_t* b) {
    asm volatile("mma.sync.aligned.m16n8k16.row.col.f32.bf16.bf16.f32 "
        "{%0,%1,%2,%3}, {%4,%5,%6,%7}, {%8,%9}, {%0,%1,%2,%3};"
        : "+f"(c[0]), "+f"(c[1]), "+f"(c[2]), "+f"(c[3])
        : "r"(a[0]), "r"(a[1]), "r"(a[2]), "r"(a[3]), "r"(b[0]), "r"(b[1]));
}

// ---------------- per-slab compute: 3-pass bf16 compensation ----------------
__device__ __forceinline__ void compute_slab(uint32_t stg, float acc[4][4][4],
                                             int wr, int wc, int lane)
{
    const uint32_t aoff = ((wr * 64 + (lane & 15)) * LDS_EL + (lane >> 4) * 8) * 2;
    const uint32_t boff = ((wc * 32 + (lane & 15)) * LDS_EL + (lane >> 4) * 8) * 2;
    #pragma unroll
    for (int ks = 0; ks < 2; ks++) {
        const uint32_t kb = ks * 32;   // 16 bf16 = 32 B
        uint32_t ahi[4][4];
        #pragma unroll
        for (int i = 0; i < 4; i++) ldm4(ahi[i], stg + aoff + kb + i * (16 * LDS_EL * 2));

        uint32_t bh[4][2];
        {
            uint32_t t0[4], t1[4];
            ldm4(t0, stg + 2 * A_SZ + boff + kb);
            ldm4(t1, stg + 2 * A_SZ + boff + kb + 16 * LDS_EL * 2);
            bh[0][0] = t0[0]; bh[0][1] = t0[2]; bh[1][0] = t0[1]; bh[1][1] = t0[3];
            bh[2][0] = t1[0]; bh[2][1] = t1[2]; bh[3][0] = t1[1]; bh[3][1] = t1[3];
        }
        #pragma unroll
        for (int j = 0; j < 4; j++)
            #pragma unroll
            for (int i = 0; i < 4; i++) mma16(acc[i][j], ahi[i], bh[j]);   // hi*hi

        {
            uint32_t t0[4], t1[4], bl[4][2];
            ldm4(t0, stg + 3 * A_SZ + boff + kb);
            ldm4(t1, stg + 3 * A_SZ + boff + kb + 16 * LDS_EL * 2);
            bl[0][0] = t0[0]; bl[0][1] = t0[2]; bl[1][0] = t0[1]; bl[1][1] = t0[3];
            bl[2][0] = t1[0]; bl[2][1] = t1[2]; bl[3][0] = t1[1]; bl[3][1] = t1[3];
            #pragma unroll
            for (int j = 0; j < 4; j++)
                #pragma unroll
                for (int i = 0; i < 4; i++) mma16(acc[i][j], ahi[i], bl[j]); // hi*lo
        }
        {
            uint32_t alo[4][4];
            #pragma unroll
            for (int i = 0; i < 4; i++) ldm4(alo[i], stg + A_SZ + aoff + kb + i * (16 * LDS_EL * 2));
            #pragma unroll
            for (int j = 0; j < 4; j++)
                #pragma unroll
                for (int i = 0; i < 4; i++) mma16(acc[i][j], alo[i], bh[j]); // lo*hi
        }
    }
}

// ---------------- pipelined GEMM segment ----------------
__device__ __forceinline__ void gemm_pipe(
    const __nv_bfloat16* __restrict__ Ah, const __nv_bfloat16* __restrict__ Al, int lda, int m0,
    const __nv_bfloat16* __restrict__ Bh, const __nv_bfloat16* __restrict__ Bl, int ldb, int n0,
    int K, uint32_t sb, float acc[4][4][4])
{
    const int tid = threadIdx.x;
    const int warp = tid >> 5, lane = tid & 31;
    const int wr = warp >> 2, wc = warp & 3;

    const __nv_bfloat16* src0 = Ah + (size_t)m0 * lda;
    const __nv_bfloat16* src1 = Al + (size_t)m0 * lda;
    const __nv_bfloat16* src2 = Bh + (size_t)n0 * ldb;
    const __nv_bfloat16* src3 = Bl + (size_t)n0 * ldb;

    auto issue = [&](int slab, int buf) {
        const int k0 = slab * 32;
        const uint32_t db = sb + buf * STAGE;
        #pragma unroll
        for (int t = 0; t < 8; t++) {
            int id   = tid + t * 256;
            int tile = id >> 9;            // 512 16B-chunks per tile
            int c    = id & 511;
            int row  = c >> 2, seg = c & 3;
            const __nv_bfloat16* s;
            if      (tile == 0) s = src0 + (size_t)row * lda + k0 + seg * 8;
            else if (tile == 1) s = src1 + (size_t)row * lda + k0 + seg * 8;
            else if (tile == 2) s = src2 + (size_t)row * ldb + k0 + seg * 8;
            else                s = src3 + (size_t)row * ldb + k0 + seg * 8;
            cp16(db + tile * A_SZ + (row * LDS_EL + seg * 8) * 2, s);
        }
        CP_COMMIT();
    };

    const int nslab = K / 32;
    issue(0, 0);
    for (int s = 0; s < nslab; s++) {
        if (s + 1 < nslab) { issue(s + 1, (s + 1) & 1); CP_WAIT(1); }
        else               { CP_WAIT(0); }
        __syncthreads();
        compute_slab(sb + (s & 1) * STAGE, acc, wr, wc, lane);
        __syncthreads();
    }
}

// ---------------- kernels ----------------
__global__ void split_kernel(const float* __restrict__ src,
                             __nv_bfloat16* __restrict__ hi,
                             __nv_bfloat16* __restrict__ lo, int n)
{
    int i = (blockIdx.x * blockDim.x + threadIdx.x) * 4;
    if (i >= n) return;
    float4 v = *(const float4*)(src + i);
    __nv_bfloat16 h[4], l[4];
    h[0] = __float2bfloat16(v.x); l[0] = __float2bfloat16(v.x - __bfloat162float(h[0]));
    h[1] = __float2bfloat16(v.y); l[1] = __float2bfloat16(v.y - __bfloat162float(h[1]));
    h[2] = __float2bfloat16(v.z); l[2] = __float2bfloat16(v.z - __bfloat162float(h[2]));
    h[3] = __float2bfloat16(v.w); l[3] = __float2bfloat16(v.w - __bfloat162float(h[3]));
    *(uint2*)(hi + i) = *(uint2*)h;
    *(uint2*)(lo + i) = *(uint2*)l;
}

// NOTE: n-block is blockIdx.x (fastest) -> one wave spans all n-blocks of few
// m-blocks, so A tiles (x/h hi+lo) hit L2 instead of DRAM on re-reads.
__global__ __launch_bounds__(256, 2)
void proj_kernel(const float* __restrict__ bias)
{
    extern __shared__ char smem[];
    uint32_t sb = smem_u32(smem);
    float acc[4][4][4] = {};

    const int m0 = blockIdx.y * 128;
    const int bx = blockIdx.x;               // 0,1 -> a; 2,3 -> b
    const bool is_a = (bx < 2);
    const int n0 = (bx & 1) * 128;
    const __nv_bfloat16* Wh = is_a ? g_wahi : g_bwhi;
    const __nv_bfloat16* Wl = is_a ? g_walo : g_bwlo;

    gemm_pipe(g_xhi, g_xlo, DM, m0, Wh, Wl, DM, n0, DM, sb, acc);

    float* dst = is_a ? g_a : g_b;
    const int warp = threadIdx.x >> 5, lane = threadIdx.x & 31;
    const int wr = warp >> 2, wc = warp & 3;
    const int gq = lane >> 2, tq = lane & 3;

    #pragma unroll
    for (int i = 0; i < 4; i++) {
        #pragma unroll
        for (int j = 0; j < 4; j++) {
            const int row = m0 + wr * 64 + i * 16 + gq;
            const int col = n0 + wc * 32 + j * 8 + tq * 2;
            float v0 = acc[i][j][0], v1 = acc[i][j][1];
            float v2 = acc[i][j][2], v3 = acc[i][j][3];
            if (is_a) {
                float b0 = bias[col], b1 = bias[col + 1];
                v0 = 1.0f / (1.0f + __expf(-(v0 + b0)));
                v1 = 1.0f / (1.0f + __expf(-(v1 + b1)));
                v2 = 1.0f / (1.0f + __expf(-(v2 + b0)));
                v3 = 1.0f / (1.0f + __expf(-(v3 + b1)));
            }
            *(float2*)&dst[(size_t)row * NS + col]       = make_float2(v0, v1);
            *(float2*)&dst[(size_t)(row + 8) * NS + col] = make_float2(v2, v3);
        }
    }
}

__global__ __launch_bounds__(256, 2)
void out_kernel(float* __restrict__ Y)
{
    extern __shared__ char smem[];
    uint32_t sb = smem_u32(smem);
    float acc[4][4][4] = {};

    const int m0 = blockIdx.y * 128;
    const int n0 = blockIdx.x * 128;

    gemm_pipe(g_hhi, g_hlo, NS, m0, g_chi, g_clo, NS, n0, NS, sb, acc); // h @ C^T
    gemm_pipe(g_xhi, g_xlo, DM, m0, g_dhi, g_dlo, DM, n0, DM, sb, acc); // x @ D^T

    const int warp = threadIdx.x >> 5, lane = threadIdx.x & 31;
    const int wr = warp >> 2, wc = warp & 3;
    const int gq = lane >> 2, tq = lane & 3;

    #pragma unroll
    for (int i = 0; i < 4; i++) {
        #pragma unroll
        for (int j = 0; j < 4; j++) {
            const int row = m0 + wr * 64 + i * 16 + gq;
            const int col = n0 + wc * 32 + j * 8 + tq * 2;
            *(float2*)&Y[(size_t)row * DM + col]       = make_float2(acc[i][j][0], acc[i][j][1]);
            *(float2*)&Y[(size_t)(row + 8) * DM + col] = make_float2(acc[i][j][2], acc[i][j][3]);
        }
    }
}

// ---------------- scan ----------------
__global__ void scan_agg()
{
    const int bc = blockIdx.x, n = threadIdx.x;
    const int b = bc / NCHUNK, c = bc % NCHUNK;
    size_t base = ((size_t)b * SEQ + (size_t)c * CHUNK) * NS + n;
    float A = 1.0f, Bv = 0.0f;
    for (int s = 0; s < CHUNK; s++) {
        size_t idx = base + (size_t)s * NS;
        float a = g_a[idx], bb = g_b[idx];
        A = a * A; Bv = a * Bv + bb;
    }
    g_Aagg[(size_t)bc * NS + n] = A;
    g_Bagg[(size_t)bc * NS + n] = Bv;
}

__global__ void scan_carry()
{
    const int b = blockIdx.x, n = threadIdx.x;
    float h = 0.0f;
    for (int c = 0; c < NCHUNK; c++) {
        size_t idx = ((size_t)b * NCHUNK + c) * NS + n;
        g_carry[idx] = h;
        h = g_Aagg[idx] * h + g_Bagg[idx];
    }
}

__global__ void scan_apply()
{
    const int bc = blockIdx.x, n = threadIdx.x;
    const int b = bc / NCHUNK, c = bc % NCHUNK;
    float h = g_carry[(size_t)bc * NS + n];
    size_t base = ((size_t)b * SEQ + (size_t)c * CHUNK) * NS + n;
    for (int s = 0; s < CHUNK; s++) {
        size_t idx = base + (size_t)s * NS;
        h = g_a[idx] * h + g_b[idx];
        __nv_bfloat16 hh = __float2bfloat16(h);
        g_hhi[idx] = hh;
        g_hlo[idx] = __float2bfloat16(h - __bfloat162float(hh));
    }
}

// ---------------- launch ----------------
extern "C" void kernel_launch(void* const* d_in, const int* in_sizes, int n_in,
                              void* d_out, int out_size)
{
    const float* x    = (const float*)d_in[0];
    const float* Wa_w = (const float*)d_in[1];
    const float* Wa_b = (const float*)d_in[2];
    const float* B_w  = (const float*)d_in[3];
    const float* C_w  = (const float*)d_in[4];
    const float* D_w  = (const float*)d_in[5];
    float* y = (float*)d_out;

    cudaFuncSetAttribute(proj_kernel, cudaFuncAttributeMaxDynamicSharedMemorySize, SMEM_TOTAL);
    cudaFuncSetAttribute(out_kernel,  cudaFuncAttributeMaxDynamicSharedMemorySize, SMEM_TOTAL);

    __nv_bfloat16 *xhi, *xlo, *wahi, *walo, *bwhi, *bwlo, *chi, *clo, *dhi, *dlo;
    cudaGetSymbolAddress((void**)&xhi,  g_xhi);  cudaGetSymbolAddress((void**)&xlo,  g_xlo);
    cudaGetSymbolAddress((void**)&wahi, g_wahi); cudaGetSymbolAddress((void**)&walo, g_walo);
    cudaGetSymbolAddress((void**)&bwhi, g_bwhi); cudaGetSymbolAddress((void**)&bwlo, g_bwlo);
    cudaGetSymbolAddress((void**)&chi,  g_chi);  cudaGetSymbolAddress((void**)&clo,  g_clo);
    cudaGetSymbolAddress((void**)&dhi,  g_dhi);  cudaGetSymbolAddress((void**)&dlo,  g_dlo);

    split_kernel<<<(M_ROWS*DM/4 + 255)/256, 256>>>(x,    xhi,  xlo,  M_ROWS*DM);
    split_kernel<<<(NS*DM/4     + 255)/256, 256>>>(Wa_w, wahi, walo, NS*DM);
    split_kernel<<<(NS*DM/4     + 255)/256, 256>>>(B_w,  bwhi, bwlo, NS*DM);
    split_kernel<<<(DM*NS/4     + 255)/256, 256>>>(C_w,  chi,  clo,  DM*NS);
    split_kernel<<<(DM*DM/4     + 255)/256, 256>>>(D_w,  dhi,  dlo,  DM*DM);

    dim3 blk(256);
    dim3 gproj(4, M_ROWS / 128);          // n-block fastest -> A reuse in L2
    proj_kernel<<<gproj, blk, SMEM_TOTAL>>>(Wa_b);

    scan_agg  <<<BATCH * NCHUNK, NS>>>();
    scan_carry<<<BATCH, NS>>>();
    scan_apply<<<BATCH * NCHUNK, NS>>>();

    dim3 gout(DM / 128, M_ROWS / 128);    // n-block fastest -> A reuse in L2
    out_kernel<<<gout, blk, SMEM_TOTAL>>>(y);
}